// round 1
// baseline (speedup 1.0000x reference)
#include <cuda_runtime.h>

// Problem constants
constexpr int Bq  = 256;          // windows
constexpr int Nt  = 343;          // tokens per window
constexpr int DIM = 192;
constexpr int H   = 6;
constexpr int HD  = 32;
constexpr int Mrows = Bq * Nt;    // 87808
constexpr float SCALE = 0.17677669529663687f;  // 32^-0.5

// Scratch (device globals: allocation-free per harness rules)
__device__ float g_Q[Bq * H * Nt * HD];
__device__ float g_K[Bq * H * Nt * HD];
__device__ float g_V[Bq * H * Nt * HD];
__device__ float g_O[Mrows * DIM];

// ---------------------------------------------------------------------------
// Tiled fp32 GEMM: C[M,NC] = A[M,192] @ B[192,NC]   (BM=BN=64, BK=48)
// MODE 0: A = x, scatter into g_Q/g_K/g_V (Q scaled)
// MODE 1: A = g_O, C = out + proj_b
// ---------------------------------------------------------------------------
template <int NC, int MODE>
__global__ void __launch_bounds__(256) gemm64(const float* __restrict__ Aarg,
                                              const float* __restrict__ Bw,
                                              const float* __restrict__ bias,
                                              float* __restrict__ Cout)
{
    __shared__ float As[64][49];   // pad to 49 to break bank conflicts
    __shared__ float Bs[48][64];

    const float* A = (MODE == 0) ? Aarg : g_O;

    const int tid = threadIdx.x;
    const int tx = tid & 15;        // 16 col groups
    const int ty = tid >> 4;        // 16 row groups
    const int row0 = blockIdx.x * 64;
    const int col0 = blockIdx.y * 64;

    float acc[4][4] = {};

    for (int k0 = 0; k0 < 192; k0 += 48) {
        // load A tile 64x48 (coalesced 48-float rows)
        #pragma unroll
        for (int i = 0; i < 12; i++) {
            int idx = tid + i * 256;
            int m = idx / 48, kk = idx - m * 48;
            As[m][kk] = A[(row0 + m) * 192 + k0 + kk];
        }
        // load B tile 48x64 (coalesced 64-float rows)
        #pragma unroll
        for (int i = 0; i < 12; i++) {
            int idx = tid + i * 256;
            int kk = idx >> 6, j = idx & 63;
            Bs[kk][j] = Bw[(k0 + kk) * NC + col0 + j];
        }
        __syncthreads();

        #pragma unroll 8
        for (int kk = 0; kk < 48; kk++) {
            float a0 = As[ty * 4 + 0][kk];
            float a1 = As[ty * 4 + 1][kk];
            float a2 = As[ty * 4 + 2][kk];
            float a3 = As[ty * 4 + 3][kk];
            float4 b4 = *(const float4*)&Bs[kk][tx * 4];
            acc[0][0] = fmaf(a0, b4.x, acc[0][0]);
            acc[0][1] = fmaf(a0, b4.y, acc[0][1]);
            acc[0][2] = fmaf(a0, b4.z, acc[0][2]);
            acc[0][3] = fmaf(a0, b4.w, acc[0][3]);
            acc[1][0] = fmaf(a1, b4.x, acc[1][0]);
            acc[1][1] = fmaf(a1, b4.y, acc[1][1]);
            acc[1][2] = fmaf(a1, b4.z, acc[1][2]);
            acc[1][3] = fmaf(a1, b4.w, acc[1][3]);
            acc[2][0] = fmaf(a2, b4.x, acc[2][0]);
            acc[2][1] = fmaf(a2, b4.y, acc[2][1]);
            acc[2][2] = fmaf(a2, b4.z, acc[2][2]);
            acc[2][3] = fmaf(a2, b4.w, acc[2][3]);
            acc[3][0] = fmaf(a3, b4.x, acc[3][0]);
            acc[3][1] = fmaf(a3, b4.y, acc[3][1]);
            acc[3][2] = fmaf(a3, b4.z, acc[3][2]);
            acc[3][3] = fmaf(a3, b4.w, acc[3][3]);
        }
        __syncthreads();
    }

    if (MODE == 0) {
        #pragma unroll
        for (int m = 0; m < 4; m++) {
            int row = row0 + ty * 4 + m;
            int bb = row / Nt;
            int n  = row - bb * Nt;
            #pragma unroll
            for (int j = 0; j < 4; j++) {
                int c = col0 + tx * 4 + j;
                int which = c / 192;
                int rem = c - which * 192;
                int hh = rem >> 5;
                int d  = rem & 31;
                float v = acc[m][j];
                if (which == 0) v *= SCALE;
                float* dst = (which == 0) ? g_Q : (which == 1) ? g_K : g_V;
                dst[((bb * H + hh) * Nt + n) * HD + d] = v;
            }
        }
    } else {
        #pragma unroll
        for (int m = 0; m < 4; m++) {
            int row = row0 + ty * 4 + m;
            #pragma unroll
            for (int j = 0; j < 4; j++) {
                int c = col0 + tx * 4 + j;
                Cout[row * 192 + c] = acc[m][j] + bias[c];
            }
        }
    }
}

// ---------------------------------------------------------------------------
// Attention: one block per (b, h). 8 warps, each warp handles 4 q-rows/pass.
// smem: K[343][33], V[343][33], qrow[8][32*4], sbuf[8][343*4]
// ---------------------------------------------------------------------------
constexpr int KP = 33;                       // K/V pitch (floats)
constexpr int VS_OFF = 11320;                // 343*33 = 11319, padded
constexpr int QR_OFF = 22640;
constexpr int SB_OFF = 23664;                // QR_OFF + 8*128
constexpr int SMEM_FLOATS = SB_OFF + 8 * 1372;   // 34640 floats = 138560 B

__global__ void __launch_bounds__(256) attn_kernel(const float* __restrict__ mask,
                                                   const float* __restrict__ rpb)
{
    extern __shared__ float sm[];
    float* Ks = sm;
    float* Vs = sm + VS_OFF;

    const int hh = blockIdx.x;
    const int b  = blockIdx.y;
    const int tid = threadIdx.x;
    const int w = tid >> 5, lane = tid & 31;

    const int base = ((b * H + hh) * Nt) * HD;
    const float* Qg = g_Q + base;
    const float* Kg = g_K + base;
    const float* Vg = g_V + base;
    const float* mk = mask + (b & 63) * (Nt * Nt);

    for (int i = tid; i < Nt * HD; i += 256) {
        int k = i >> 5, d = i & 31;
        Ks[k * KP + d] = Kg[i];
        Vs[k * KP + d] = Vg[i];
    }
    __syncthreads();

    float* qw = sm + QR_OFF + w * 128;    // [d*4 + m]
    float* sw = sm + SB_OFF + w * 1372;   // [k*4 + m]

    for (int q0 = w * 4; q0 < Nt; q0 += 32) {
        const bool v1 = (q0 + 1) < Nt, v2 = (q0 + 2) < Nt, v3 = (q0 + 3) < Nt;
        // stage 4 q rows transposed: qw[d*4+m]
        float4 qv;
        qv.x = Qg[q0 * HD + lane];
        qv.y = v1 ? Qg[(q0 + 1) * HD + lane] : 0.f;
        qv.z = v2 ? Qg[(q0 + 2) * HD + lane] : 0.f;
        qv.w = v3 ? Qg[(q0 + 3) * HD + lane] : 0.f;
        *(float4*)(qw + lane * 4) = qv;
        __syncwarp();

        int iq[4], jq[4], zq[4];
        #pragma unroll
        for (int m = 0; m < 4; m++) {
            int q = q0 + m; if (q >= Nt) q = 0;   // clamp keeps rpb index in range
            jq[m] = q / 49; iq[m] = (q / 7) % 7; zq[m] = q % 7;
        }

        // ---- S = q k^T + bias + mask ----
        for (int t = 0; t < 11; t++) {
            int k = t * 32 + lane;
            if (k < Nt) {
                float a0 = 0.f, a1 = 0.f, a2 = 0.f, a3 = 0.f;
                const float* kr = Ks + k * KP;
                #pragma unroll
                for (int d = 0; d < 32; d++) {
                    float kv = kr[d];
                    float4 q4 = *(const float4*)(qw + d * 4);
                    a0 = fmaf(q4.x, kv, a0);
                    a1 = fmaf(q4.y, kv, a1);
                    a2 = fmaf(q4.z, kv, a2);
                    a3 = fmaf(q4.w, kv, a3);
                }
                int jk = k / 49, ik = (k / 7) % 7, zk = k % 7;
                float accv[4] = {a0, a1, a2, a3};
                float sv[4];
                #pragma unroll
                for (int m = 0; m < 4; m++) {
                    int idx = (iq[m] - ik + 6) * 169 + (jq[m] - jk + 6) * 13 + (zq[m] - zk + 6);
                    float bv = rpb[idx * H + hh];
                    int q = q0 + m;
                    float mv = (q < Nt) ? mk[q * Nt + k] : 0.f;
                    sv[m] = accv[m] + bv + mv;
                }
                *(float4*)(sw + k * 4) = make_float4(sv[0], sv[1], sv[2], sv[3]);
            }
        }
        __syncwarp();

        // ---- softmax over k (per row) ----
        float mx0 = -1e30f, mx1 = -1e30f, mx2 = -1e30f, mx3 = -1e30f;
        for (int t = 0; t < 11; t++) {
            int k = t * 32 + lane;
            if (k < Nt) {
                float4 vv = *(const float4*)(sw + k * 4);
                mx0 = fmaxf(mx0, vv.x); mx1 = fmaxf(mx1, vv.y);
                mx2 = fmaxf(mx2, vv.z); mx3 = fmaxf(mx3, vv.w);
            }
        }
        #pragma unroll
        for (int off = 16; off; off >>= 1) {
            mx0 = fmaxf(mx0, __shfl_xor_sync(0xffffffffu, mx0, off));
            mx1 = fmaxf(mx1, __shfl_xor_sync(0xffffffffu, mx1, off));
            mx2 = fmaxf(mx2, __shfl_xor_sync(0xffffffffu, mx2, off));
            mx3 = fmaxf(mx3, __shfl_xor_sync(0xffffffffu, mx3, off));
        }
        float s0 = 0.f, s1 = 0.f, s2 = 0.f, s3 = 0.f;
        for (int t = 0; t < 11; t++) {
            int k = t * 32 + lane;
            if (k < Nt) {
                float4 vv = *(float4*)(sw + k * 4);
                vv.x = __expf(vv.x - mx0);
                vv.y = __expf(vv.y - mx1);
                vv.z = __expf(vv.z - mx2);
                vv.w = __expf(vv.w - mx3);
                *(float4*)(sw + k * 4) = vv;
                s0 += vv.x; s1 += vv.y; s2 += vv.z; s3 += vv.w;
            }
        }
        #pragma unroll
        for (int off = 16; off; off >>= 1) {
            s0 += __shfl_xor_sync(0xffffffffu, s0, off);
            s1 += __shfl_xor_sync(0xffffffffu, s1, off);
            s2 += __shfl_xor_sync(0xffffffffu, s2, off);
            s3 += __shfl_xor_sync(0xffffffffu, s3, off);
        }
        float r0 = 1.f / s0, r1 = 1.f / s1, r2 = 1.f / s2, r3 = 1.f / s3;
        __syncwarp();

        // ---- O = P @ V  (lane = output dim d) ----
        float o0 = 0.f, o1 = 0.f, o2 = 0.f, o3 = 0.f;
        #pragma unroll 7
        for (int k = 0; k < Nt; k++) {
            float vv = Vs[k * KP + lane];
            float4 p = *(const float4*)(sw + k * 4);
            o0 = fmaf(p.x, vv, o0);
            o1 = fmaf(p.y, vv, o1);
            o2 = fmaf(p.z, vv, o2);
            o3 = fmaf(p.w, vv, o3);
        }
        int ob = (b * Nt + q0) * DIM + hh * HD + lane;
        g_O[ob] = o0 * r0;
        if (v1) g_O[ob + DIM]     = o1 * r1;
        if (v2) g_O[ob + 2 * DIM] = o2 * r2;
        if (v3) g_O[ob + 3 * DIM] = o3 * r3;
        __syncwarp();
    }
}

// ---------------------------------------------------------------------------
extern "C" void kernel_launch(void* const* d_in, const int* in_sizes, int n_in,
                              void* d_out, int out_size)
{
    const float* x     = (const float*)d_in[0];
    const float* mask  = (const float*)d_in[1];
    const float* qkv_w = (const float*)d_in[2];
    const float* rpb   = (const float*)d_in[3];
    const float* projw = (const float*)d_in[4];
    const float* projb = (const float*)d_in[5];
    float* out = (float*)d_out;

    // 1) QKV projection (Q pre-scaled), scatter to [b,h,n,d] scratch
    dim3 g1(Mrows / 64, 576 / 64);
    gemm64<576, 0><<<g1, 256>>>(x, qkv_w, nullptr, nullptr);

    // 2) fused attention (bias gather + mask + softmax + PV)
    cudaFuncSetAttribute(attn_kernel, cudaFuncAttributeMaxDynamicSharedMemorySize,
                         SMEM_FLOATS * 4);
    dim3 g2(H, Bq);
    attn_kernel<<<g2, 256, SMEM_FLOATS * 4>>>(mask, rpb);

    // 3) output projection + bias
    dim3 g3(Mrows / 64, 192 / 64);
    gemm64<192, 1><<<g3, 256>>>(nullptr, projw, projb, out);
}